// round 5
// baseline (speedup 1.0000x reference)
#include <cuda_runtime.h>
#include <cstdint>

#define N_NODES 50000
#define N_EDGES 800000
#define D 128
#define BN_EPS 1e-5f

// ---------------- scratch (no allocations allowed) ----------------
__device__ double g_sum[D];
__device__ double g_sumsq[D];

// ---------------- K1: init out = (1+eps)*h*norm^2, zero stats ----------------
__global__ void __launch_bounds__(256) k_init(
    const float* __restrict__ h, const float* __restrict__ norm,
    const float* __restrict__ eps_p, float* __restrict__ out)
{
    int i4 = blockIdx.x * blockDim.x + threadIdx.x;
    if (i4 < D) { g_sum[i4] = 0.0; g_sumsq[i4] = 0.0; }
    if (i4 >= (N_NODES * D) / 4) return;
    int row = i4 >> 5;                       // D/4 = 32 float4 per row
    float n = norm[row];
    float s = (1.0f + eps_p[0]) * n * n;
    float4 hv = ((const float4*)h)[i4];
    ((float4*)out)[i4] = make_float4(hv.x * s, hv.y * s, hv.z * s, hv.w * s);
}

// ---------------- K2: edge scatter (warp per edge) ----------------
// v = h[src] * norm[src] * norm[dst], red-add into out[dst].
__global__ void __launch_bounds__(256) k_edges(
    const float* __restrict__ h, const float* __restrict__ norm,
    const int* __restrict__ src, const int* __restrict__ dst,
    float* __restrict__ out)
{
    long long t = (long long)blockIdx.x * blockDim.x + threadIdx.x;
    int e    = (int)(t >> 5);
    int lane = (int)(t & 31);
    if (e >= N_EDGES) return;

    int s = __ldg(src + e);          // warp-uniform
    int d = __ldg(dst + e);          // warp-uniform
    float w = __ldg(norm + s) * __ldg(norm + d);   // warp-uniform

    const float4 hv = __ldg((const float4*)(h + (size_t)s * D) + lane);
    float4 v = make_float4(hv.x * w, hv.y * w, hv.z * w, hv.w * w);

    float* p = out + (size_t)d * D + lane * 4;
    asm volatile("red.global.add.v4.f32 [%0], {%1,%2,%3,%4};"
                 :: "l"(p), "f"(v.x), "f"(v.y), "f"(v.z), "f"(v.w)
                 : "memory");
}

// ---------------- K3: read-only per-channel stats ----------------
#define ROWS_PER_BLOCK 64
__global__ void __launch_bounds__(128) k_stats_partial(
    const float* __restrict__ out)
{
    int c    = threadIdx.x;                 // channel 0..127
    int row0 = blockIdx.x * ROWS_PER_BLOCK;

    float lsum = 0.f, lsq = 0.f;
#pragma unroll 8
    for (int r = 0; r < ROWS_PER_BLOCK; r++) {
        int row = row0 + r;
        if (row >= N_NODES) break;
        float v = __ldg(out + (size_t)row * D + c);
        lsum += v;
        lsq  += v * v;
    }
    atomicAdd(&g_sum[c],   (double)lsum);
    atomicAdd(&g_sumsq[c], (double)lsq);
}

// ---------------- K4: finalize stats per block + BN apply + ReLU ----------------
__global__ void __launch_bounds__(256) k_bn(
    const float* __restrict__ gamma, const float* __restrict__ beta,
    float* __restrict__ out)
{
    __shared__ float4 s_scale4[D / 4];
    __shared__ float4 s_bias4[D / 4];

    int tid = threadIdx.x;
    if (tid < D) {
        double mu  = g_sum[tid]   / (double)N_NODES;
        double var = g_sumsq[tid] / (double)N_NODES - mu * mu;
        double rstd = 1.0 / sqrt(var + (double)BN_EPS);
        float sc = gamma[tid] * (float)rstd;
        float bi = beta[tid] - (float)mu * sc;
        ((float*)s_scale4)[tid] = sc;
        ((float*)s_bias4)[tid]  = bi;
    }
    __syncthreads();

    int i4 = blockIdx.x * blockDim.x + tid;
    if (i4 >= (N_NODES * D) / 4) return;
    int c4 = i4 & (D / 4 - 1);
    float4 sc = s_scale4[c4];
    float4 bi = s_bias4[c4];
    float4 x = ((float4*)out)[i4];
    x.x = fmaxf(fmaf(x.x, sc.x, bi.x), 0.f);
    x.y = fmaxf(fmaf(x.y, sc.y, bi.y), 0.f);
    x.z = fmaxf(fmaf(x.z, sc.z, bi.z), 0.f);
    x.w = fmaxf(fmaf(x.w, sc.w, bi.w), 0.f);
    ((float4*)out)[i4] = x;
}

// ---------------- launch ----------------
extern "C" void kernel_launch(void* const* d_in, const int* in_sizes, int n_in,
                              void* d_out, int out_size)
{
    const float* h     = (const float*)d_in[0];
    const float* norm  = (const float*)d_in[1];
    const float* eps   = (const float*)d_in[2];
    const float* gamma = (const float*)d_in[3];
    const float* beta  = (const float*)d_in[4];
    const int*   src   = (const int*)d_in[5];
    const int*   dst   = (const int*)d_in[6];
    float* out = (float*)d_out;

    (void)in_sizes; (void)n_in; (void)out_size;

    const int total4 = (N_NODES * D) / 4;            // 1.6M float4
    k_init<<<(total4 + 255) / 256, 256>>>(h, norm, eps, out);

    const long long ethreads = (long long)N_EDGES * 32;
    k_edges<<<(unsigned)((ethreads + 255) / 256), 256>>>(h, norm, src, dst, out);

    const int sblocks = (N_NODES + ROWS_PER_BLOCK - 1) / ROWS_PER_BLOCK;
    k_stats_partial<<<sblocks, 128>>>(out);

    k_bn<<<(total4 + 255) / 256, 256>>>(gamma, beta, out);
}

// round 6
// speedup vs baseline: 1.3639x; 1.3639x over previous
#include <cuda_runtime.h>
#include <cstdint>

#define N_NODES 50000
#define N_EDGES 800000
#define D 128
#define BN_EPS 1e-5f

// ---------------- scratch (no allocations allowed) ----------------
__device__ double g_sum[D];
__device__ double g_sumsq[D];
__device__ float  g_scale[D];
__device__ float  g_bias[D];
__device__ unsigned g_done;

// ---------------- K1: init out = (1+eps)*h*norm^2, zero stats ----------------
__global__ void __launch_bounds__(256) k_init(
    const float* __restrict__ h, const float* __restrict__ norm,
    const float* __restrict__ eps_p, float* __restrict__ out)
{
    int i4 = blockIdx.x * blockDim.x + threadIdx.x;
    if (i4 < D) { g_sum[i4] = 0.0; g_sumsq[i4] = 0.0; }
    if (i4 == 0) g_done = 0;
    if (i4 >= (N_NODES * D) / 4) return;
    int row = i4 >> 5;                       // D/4 = 32 float4 per row
    float n = norm[row];
    float s = (1.0f + eps_p[0]) * n * n;
    float4 hv = ((const float4*)h)[i4];
    ((float4*)out)[i4] = make_float4(hv.x * s, hv.y * s, hv.z * s, hv.w * s);
}

// ---------------- K2: edge scatter (warp per edge) ----------------
// v = h[src] * norm[src] * norm[dst], red-add into out[dst].
__global__ void __launch_bounds__(256) k_edges(
    const float* __restrict__ h, const float* __restrict__ norm,
    const int* __restrict__ src, const int* __restrict__ dst,
    float* __restrict__ out)
{
    long long t = (long long)blockIdx.x * blockDim.x + threadIdx.x;
    int e    = (int)(t >> 5);
    int lane = (int)(t & 31);
    if (e >= N_EDGES) return;

    int s = __ldg(src + e);          // warp-uniform
    int d = __ldg(dst + e);          // warp-uniform
    float w = __ldg(norm + s) * __ldg(norm + d);   // warp-uniform

    const float4 hv = __ldg((const float4*)(h + (size_t)s * D) + lane);
    float4 v = make_float4(hv.x * w, hv.y * w, hv.z * w, hv.w * w);

    float* p = out + (size_t)d * D + lane * 4;
    asm volatile("red.global.add.v4.f32 [%0], {%1,%2,%3,%4};"
                 :: "l"(p), "f"(v.x), "f"(v.y), "f"(v.z), "f"(v.w)
                 : "memory");
}

// ---------------- K3: read-only stats + last-block finalize ----------------
#define ROWS_PER_BLOCK 64
__global__ void __launch_bounds__(128) k_stats_partial(
    const float* __restrict__ gamma, const float* __restrict__ beta,
    const float* __restrict__ out, int nblocks)
{
    int c    = threadIdx.x;                 // channel 0..127
    int row0 = blockIdx.x * ROWS_PER_BLOCK;

    float lsum = 0.f, lsq = 0.f;
#pragma unroll 8
    for (int r = 0; r < ROWS_PER_BLOCK; r++) {
        int row = row0 + r;
        if (row >= N_NODES) break;
        float v = __ldg(out + (size_t)row * D + c);
        lsum += v;
        lsq  += v * v;
    }
    atomicAdd(&g_sum[c],   (double)lsum);
    atomicAdd(&g_sumsq[c], (double)lsq);

    // last block finalizes scale/bias exactly once
    __threadfence();
    __syncthreads();
    __shared__ int s_last;
    if (c == 0) {
        unsigned t = atomicAdd(&g_done, 1u);
        s_last = (t == (unsigned)(nblocks - 1));
    }
    __syncthreads();
    if (s_last) {
        double su  = __ldcg(&g_sum[c]);
        double ssq = __ldcg(&g_sumsq[c]);
        double mu  = su / (double)N_NODES;
        double var = ssq / (double)N_NODES - mu * mu;
        double rstd = 1.0 / sqrt(var + (double)BN_EPS);
        float sc = gamma[c] * (float)rstd;
        g_scale[c] = sc;
        g_bias[c]  = beta[c] - (float)mu * sc;
    }
}

// ---------------- K4: BN apply + ReLU (pure memory pass) ----------------
__global__ void __launch_bounds__(256) k_bn(float* __restrict__ out)
{
    __shared__ float4 s_scale4[D / 4];
    __shared__ float4 s_bias4[D / 4];

    int tid = threadIdx.x;
    if (tid < D) {
        ((float*)s_scale4)[tid] = g_scale[tid];
        ((float*)s_bias4)[tid]  = g_bias[tid];
    }
    __syncthreads();

    int i4 = blockIdx.x * blockDim.x + tid;
    if (i4 >= (N_NODES * D) / 4) return;
    int c4 = i4 & (D / 4 - 1);
    float4 sc = s_scale4[c4];
    float4 bi = s_bias4[c4];
    float4 x = ((float4*)out)[i4];
    x.x = fmaxf(fmaf(x.x, sc.x, bi.x), 0.f);
    x.y = fmaxf(fmaf(x.y, sc.y, bi.y), 0.f);
    x.z = fmaxf(fmaf(x.z, sc.z, bi.z), 0.f);
    x.w = fmaxf(fmaf(x.w, sc.w, bi.w), 0.f);
    ((float4*)out)[i4] = x;
}

// ---------------- launch ----------------
extern "C" void kernel_launch(void* const* d_in, const int* in_sizes, int n_in,
                              void* d_out, int out_size)
{
    const float* h     = (const float*)d_in[0];
    const float* norm  = (const float*)d_in[1];
    const float* eps   = (const float*)d_in[2];
    const float* gamma = (const float*)d_in[3];
    const float* beta  = (const float*)d_in[4];
    const int*   src   = (const int*)d_in[5];
    const int*   dst   = (const int*)d_in[6];
    float* out = (float*)d_out;

    (void)in_sizes; (void)n_in; (void)out_size;

    const int total4 = (N_NODES * D) / 4;            // 1.6M float4
    k_init<<<(total4 + 255) / 256, 256>>>(h, norm, eps, out);

    const long long ethreads = (long long)N_EDGES * 32;
    k_edges<<<(unsigned)((ethreads + 255) / 256), 256>>>(h, norm, src, dst, out);

    const int sblocks = (N_NODES + ROWS_PER_BLOCK - 1) / ROWS_PER_BLOCK;
    k_stats_partial<<<sblocks, 128>>>(gamma, beta, out, sblocks);

    k_bn<<<(total4 + 255) / 256, 256>>>(out);
}